// round 13
// baseline (speedup 1.0000x reference)
#include <cuda_runtime.h>
#include <cuda_bf16.h>
#include <math.h>
#include <stdint.h>

#define MAXN    8192
#define TILE    128
#define RSTRIDE 272                                // 256B row + 16B pad (conflict-free ldmatrix)
#define ARRB    (128 * RSTRIDE)                    // 34816 B per tile array
#define GRID    148
#define NTHR    512
#define MAXG    (MAXN / 32)                        // 256 label groups

// ---------------- device scratch (allocation-free) ----------------
__device__ __nv_bfloat16 g_hi[MAXN * 128];
__device__ __nv_bfloat16 g_lo[MAXN * 128];
__device__ int   g_c0;
__device__ float g_part[GRID * 2];
__device__ int   g_done;                           // final-sum ticket (self-reset)

__device__ __forceinline__ uint32_t smem_u32(const void* p) {
    uint32_t a;
    asm("{ .reg .u64 t; cvta.to.shared.u64 t, %1; cvt.u32.u64 %0, t; }" : "=r"(a) : "l"(p));
    return a;
}
__device__ __forceinline__ void ldsm_x4(uint32_t* r, uint32_t addr) {
    asm volatile("ldmatrix.sync.aligned.m8n8.x4.shared.b16 {%0,%1,%2,%3}, [%4];"
                 : "=r"(r[0]), "=r"(r[1]), "=r"(r[2]), "=r"(r[3]) : "r"(addr));
}
__device__ __forceinline__ void mma16816(float* d, const uint32_t* a, const uint32_t* b) {
    asm volatile("mma.sync.aligned.m16n8k16.row.col.f32.bf16.bf16.f32 "
                 "{%0,%1,%2,%3}, {%4,%5,%6,%7}, {%8,%9}, {%0,%1,%2,%3};"
                 : "+f"(d[0]), "+f"(d[1]), "+f"(d[2]), "+f"(d[3])
                 : "r"(a[0]), "r"(a[1]), "r"(a[2]), "r"(a[3]), "r"(b[0]), "r"(b[1]));
}
__device__ __forceinline__ void cp16(uint32_t dst, const void* src, bool v) {
    asm volatile("cp.async.cg.shared.global [%0], [%1], 16, %2;"
                 :: "r"(dst), "l"(src), "r"(v ? 16 : 0) : "memory");
}
#define CP_COMMIT()  asm volatile("cp.async.commit_group;" ::: "memory")
#define CP_WAIT1()   asm volatile("cp.async.wait_group 1;" ::: "memory")
#define CP_WAIT0()   asm volatile("cp.async.wait_group 0;" ::: "memory")

// ---------------------------------------------------------------------------
// Kernel 1: prep — per-block redundant group counts + scan, then normalize/
// split/scatter this block's row slice into grouped order. 148 blocks x 256.
// ---------------------------------------------------------------------------
__global__ __launch_bounds__(256) void prep_kernel(
    const float* __restrict__ emb, const int* __restrict__ label, int N)
{
    const int tid = threadIdx.x, wid = tid >> 5, lane = tid & 31;
    const int NG = (N + 31) >> 5;

    __shared__ int s_pref[MAXG];
    __shared__ int s_wsum[8];
    __shared__ int s_c0;

    {
        int c = 0;
        if (tid < NG) {
            const int b0 = tid * 32;
            if (b0 + 32 <= N) {
                const int4* p = (const int4*)(label + b0);
                #pragma unroll
                for (int i = 0; i < 8; i++) {
                    const int4 v = p[i];
                    c += (v.x == 0) + (v.y == 0) + (v.z == 0) + (v.w == 0);
                }
            } else {
                for (int i = b0; i < N; i++) c += (label[i] == 0);
            }
        }
        int incl = c;
        #pragma unroll
        for (int o = 1; o < 32; o <<= 1) {
            int v = __shfl_up_sync(0xffffffffu, incl, o);
            if (lane >= o) incl += v;
        }
        if (lane == 31) s_wsum[wid] = incl;
        __syncthreads();
        if (wid == 0 && lane < 8) {
            int v = s_wsum[lane];
            #pragma unroll
            for (int o = 1; o < 8; o <<= 1) {
                int u = __shfl_up_sync(0xffu, v, o);
                if (lane >= o) v += u;
            }
            s_wsum[lane] = v;
        }
        __syncthreads();
        incl += (wid > 0) ? s_wsum[wid - 1] : 0;
        if (tid < NG) s_pref[tid] = incl - c;
        if (tid == 0) {
            s_c0 = s_wsum[7];
            if (blockIdx.x == 0) g_c0 = s_wsum[7];
        }
        __syncthreads();
    }
    const int C0 = s_c0;

    const int rowsPer = (N + gridDim.x - 1) / gridDim.x;
    const int r0 = blockIdx.x * rowsPer;
    const int r1 = min(r0 + rowsPer, N);
    for (int r = r0 + wid; r < r1; r += 8) {
        const int g = r >> 5;
        const int idx = g * 32 + lane;
        const int l = (idx < N) ? label[idx] : 1;
        const unsigned bal = __ballot_sync(0xffffffffu, l == 0);
        const int below = __popc(bal & ((1u << (r & 31)) - 1u));
        const int myl = __shfl_sync(0xffffffffu, l, r & 31);
        const int rank0 = s_pref[g] + below;
        const int dst = (myl == 0) ? rank0 : C0 + (r - rank0);

        float4 v = ((const float4*)(emb + (size_t)r * 128))[lane];
        float ss = v.x * v.x + v.y * v.y + v.z * v.z + v.w * v.w;
        #pragma unroll
        for (int o = 16; o; o >>= 1) ss += __shfl_xor_sync(0xffffffffu, ss, o);
        const float scale = 1.0f / fmaxf(sqrtf(ss), 1e-12f);
        float x[4] = {v.x * scale, v.y * scale, v.z * scale, v.w * scale};
        __nv_bfloat16 h[4], lo[4];
        #pragma unroll
        for (int i = 0; i < 4; i++) {
            h[i]  = __float2bfloat16(x[i]);
            lo[i] = __float2bfloat16(x[i] - __bfloat162float(h[i]));
        }
        uint2 ph, pl;
        ph.x = (uint32_t)__bfloat16_as_ushort(h[0])  | ((uint32_t)__bfloat16_as_ushort(h[1])  << 16);
        ph.y = (uint32_t)__bfloat16_as_ushort(h[2])  | ((uint32_t)__bfloat16_as_ushort(h[3])  << 16);
        pl.x = (uint32_t)__bfloat16_as_ushort(lo[0]) | ((uint32_t)__bfloat16_as_ushort(lo[1]) << 16);
        pl.y = (uint32_t)__bfloat16_as_ushort(lo[2]) | ((uint32_t)__bfloat16_as_ushort(lo[3]) << 16);
        ((uint2*)(g_hi + (size_t)dst * 128))[lane] = ph;
        ((uint2*)(g_lo + (size_t)dst * 128))[lane] = pl;
    }
}

// ---------------------------------------------------------------------------
// Kernel 2: persistent HMMA split-GEMM, 512 threads (16 warps 4x4, 32x32/warp)
// Term-major MMA ordering: 8 independent accumulators between reuses.
// ---------------------------------------------------------------------------
__device__ __forceinline__ void issue_tile(uint32_t dHi, uint32_t dLo, int b0, int N, int tid) {
    #pragma unroll
    for (int it = 0; it < 4; it++) {
        const int c = tid + it * NTHR;
        const int row = c >> 4, col16 = c & 15;
        const uint32_t off = (uint32_t)row * RSTRIDE + (uint32_t)col16 * 16;
        const int gr = b0 * TILE + row;
        const bool v = gr < N;
        const size_t g = (size_t)min(gr, N - 1) * 128 + col16 * 8;
        cp16(dHi + off, g_hi + g, v);
        cp16(dLo + off, g_lo + g, v);
    }
}

__global__ __launch_bounds__(NTHR, 1) void tile_pers_kernel(float* __restrict__ out, int N, int T) {
    const int tid = threadIdx.x, wid = tid >> 5, lane = tid & 31;
    const int C0 = g_c0;
    const int bx  = C0 >> 7;                       // label-boundary tile index
    const int C1s = (C0 + TILE - 1) >> 7;
    const int F0  = bx;
    const int nvalid = T * (T + 1) / 2 - F0 * (T - C1s);
    const int G = gridDim.x;
    const int q = nvalid / G, rmd = nvalid % G;
    const int start = blockIdx.x * q + min((int)blockIdx.x, rmd);
    const int end   = start + q + ((int)blockIdx.x < rmd ? 1 : 0);

    extern __shared__ char dsm[];
    const uint32_t base = smem_u32(dsm);
    const uint32_t sAh = base, sAl = base + ARRB;
    const uint32_t sBh0 = base + 2 * ARRB, sBl0 = base + 3 * ARRB;
    const uint32_t sBh1 = base + 4 * ARRB, sBl1 = base + 5 * ARRB;
    float* red = (float*)(dsm + 6 * ARRB);

    const int wm = wid & 3, wn = wid >> 2;         // 4x4 warp grid, 32x32 per warp
    const uint32_t aLaneOff = (uint32_t)(wm * 32 + (lane & 15)) * RSTRIDE + (uint32_t)(lane >> 4) * 16;
    const uint32_t bLaneOff = (uint32_t)(wn * 32 + ((lane >> 4) & 1) * 8 + (lane & 7)) * RSTRIDE
                            + (uint32_t)((lane >> 3) & 1) * 16;
    const int rIn = lane >> 2, cIn = (lane & 3) * 2;

    float s0 = 0.0f, s1 = 0.0f;

    if (start < end) {
        int bi = 0, bj = 0, k = 0;
        for (;;) {
            const int rowEnd = (bi < F0) ? C1s : T;
            const int cnt = rowEnd - bi;
            if (k + cnt > start) { bj = bi + (start - k); break; }
            k += cnt; bi++;
        }
        int pbi = bi, pbj = bj;
        if (pbi != pbj) issue_tile(sBh0, sBl0, pbj, N, tid);
        CP_COMMIT();

        int curA = -1;
        for (int idx = start; idx < end; idx++) {
            const int buf = (idx - start) & 1;
            const uint32_t cBh = buf ? sBh1 : sBh0, cBl = buf ? sBl1 : sBl0;
            const uint32_t nBh = buf ? sBh0 : sBh1, nBl = buf ? sBl0 : sBl1;
            const bool diag = (bi == bj);

            if (idx + 1 < end) {
                pbj++;
                const int rowEnd = (pbi < F0) ? C1s : T;
                if (pbj >= rowEnd) { pbi++; pbj = pbi; }
                if (pbi != pbj) issue_tile(nBh, nBl, pbj, N, tid);
            }
            CP_COMMIT();
            CP_WAIT1();
            __syncthreads();

            if (bi != curA) {
                issue_tile(sAh, sAl, bi, N, tid);
                CP_COMMIT();
                CP_WAIT0();
                curA = bi;
                __syncthreads();
            }

            const uint32_t bH = diag ? sAh : cBh;
            const uint32_t bL = diag ? sAl : cBl;
            const int rb = bi * TILE, cb = bj * TILE;
            const int wr0 = rb + wm * 32, wc0 = cb + wn * 32;
            const bool boundary = (bi == bx) || (bj == bx) || (rb + TILE > N) || (cb + TILE > N);
            const bool skipWarp = (wr0 > wc0 + 31) || (wr0 + 31 < C0 && wc0 >= C0);

            if (!skipWarp) {
                float acc[2][4][4];
                #pragma unroll
                for (int mt = 0; mt < 2; mt++)
                    #pragma unroll
                    for (int nt = 0; nt < 4; nt++)
                        #pragma unroll
                        for (int p = 0; p < 4; p++) acc[mt][nt][p] = 0.0f;

                #pragma unroll
                for (int kk = 0; kk < 8; kk++) {
                    const uint32_t kB = (uint32_t)kk * 32;
                    uint32_t ah[2][4], al[2][4], bh[2][4], bl[2][4];
                    #pragma unroll
                    for (int mt = 0; mt < 2; mt++) {
                        const uint32_t ao = aLaneOff + (uint32_t)mt * 16 * RSTRIDE + kB;
                        ldsm_x4(ah[mt], sAh + ao);
                        ldsm_x4(al[mt], sAl + ao);
                    }
                    #pragma unroll
                    for (int np = 0; np < 2; np++) {
                        const uint32_t bo = bLaneOff + (uint32_t)np * 16 * RSTRIDE + kB;
                        ldsm_x4(bh[np], bH + bo);
                        ldsm_x4(bl[np], bL + bo);
                    }
                    // term-major: 8 independent accs between reuses of any acc;
                    // per-acc order stays hh(k), hl(k), lh(k) -> bitwise-identical result
                    #pragma unroll
                    for (int mt = 0; mt < 2; mt++)
                        #pragma unroll
                        for (int nt = 0; nt < 4; nt++)
                            mma16816(acc[mt][nt], ah[mt], &bh[nt >> 1][(nt & 1) * 2]);
                    #pragma unroll
                    for (int mt = 0; mt < 2; mt++)
                        #pragma unroll
                        for (int nt = 0; nt < 4; nt++)
                            mma16816(acc[mt][nt], ah[mt], &bl[nt >> 1][(nt & 1) * 2]);
                    #pragma unroll
                    for (int mt = 0; mt < 2; mt++)
                        #pragma unroll
                        for (int nt = 0; nt < 4; nt++)
                            mma16816(acc[mt][nt], al[mt], &bh[nt >> 1][(nt & 1) * 2]);
                }

                if (!boundary && !diag) {
                    float t = 0.0f;
                    #pragma unroll
                    for (int mt = 0; mt < 2; mt++)
                        #pragma unroll
                        for (int nt = 0; nt < 4; nt++)
                            #pragma unroll
                            for (int p = 0; p < 4; p++)
                                t += __expf(acc[mt][nt][p] * 10.0f);
                    if (rb < C0) s0 += t; else s1 += t;
                } else if (!boundary) {
                    float t = 0.0f;
                    #pragma unroll
                    for (int mt = 0; mt < 2; mt++)
                        #pragma unroll
                        for (int nt = 0; nt < 4; nt++) {
                            const int gi0 = wr0 + mt * 16, gj0 = wc0 + nt * 8;
                            if (gi0 >= gj0 + 7) continue;
                            #pragma unroll
                            for (int p = 0; p < 4; p++) {
                                const int gi = gi0 + rIn + (p >> 1) * 8;
                                const int gj = gj0 + cIn + (p & 1);
                                if (gi < gj) t += __expf(acc[mt][nt][p] * 10.0f);
                            }
                        }
                    if (rb < C0) s0 += t; else s1 += t;
                } else {
                    #pragma unroll
                    for (int mt = 0; mt < 2; mt++)
                        #pragma unroll
                        for (int nt = 0; nt < 4; nt++) {
                            const int gi0 = wr0 + mt * 16, gj0 = wc0 + nt * 8;
                            if (gi0 >= gj0 + 7) continue;
                            if (gi0 + 15 < C0 && gj0 >= C0) continue;
                            #pragma unroll
                            for (int p = 0; p < 4; p++) {
                                const int gi = gi0 + rIn + (p >> 1) * 8;
                                const int gj = gj0 + cIn + (p & 1);
                                const bool i0 = gi < C0;
                                if (gi < N && gj < N && gi < gj && ((gj < C0) == i0)) {
                                    const float e = __expf(acc[mt][nt][p] * 10.0f);
                                    if (i0) s0 += e; else s1 += e;
                                }
                            }
                        }
                }
            }
            __syncthreads();

            bj++;
            const int rowEnd = (bi < F0) ? C1s : T;
            if (bj >= rowEnd) { bi++; bj = bi; }
        }
    }

    // per-block deterministic reduction (512 threads)
    red[tid] = s0; __syncthreads();
    for (int o = 256; o; o >>= 1) { if (tid < o) red[tid] += red[tid + o]; __syncthreads(); }
    if (tid == 0) g_part[blockIdx.x * 2] = red[0];
    __syncthreads();
    red[tid] = s1; __syncthreads();
    for (int o = 256; o; o >>= 1) { if (tid < o) red[tid] += red[tid + o]; __syncthreads(); }
    if (tid == 0) g_part[blockIdx.x * 2 + 1] = red[0];

    // last-block final reduction (ticket; nobody waits -> hang-free)
    __shared__ int s_ticket;
    __threadfence();
    if (tid == 0) s_ticket = atomicAdd(&g_done, 1);
    __syncthreads();
    if (s_ticket == G - 1) {
        __threadfence();
        float t0 = 0.0f, t1 = 0.0f;
        for (int b = tid; b < G; b += NTHR) { t0 += g_part[2 * b]; t1 += g_part[2 * b + 1]; }
        red[tid] = t0; __syncthreads();
        for (int o = 256; o; o >>= 1) { if (tid < o) red[tid] += red[tid + o]; __syncthreads(); }
        t0 = red[0]; __syncthreads();
        red[tid] = t1; __syncthreads();
        for (int o = 256; o; o >>= 1) { if (tid < o) red[tid] += red[tid + o]; __syncthreads(); }
        if (tid == 0) {
            const int c0n = C0, c1n = N - C0;
            float res = 0.0f;
            if (c0n > 1) res += 2.0f * t0 / (float)(c0n - 1);
            if (c1n > 1) res += 2.0f * red[0] / (float)(c1n - 1);
            out[0] = res;
            g_done = 0;                            // reset for next graph replay
        }
    }
}

// ---------------------------------------------------------------------------
extern "C" void kernel_launch(void* const* d_in, const int* in_sizes, int n_in,
                              void* d_out, int out_size) {
    const float* emb   = (const float*)d_in[0];
    const int*   label = (const int*)d_in[1];
    const int N = in_sizes[1];
    const int T = (N + TILE - 1) / TILE;
    const int dyn = 6 * ARRB + 2048;               // 210944 B

    cudaFuncSetAttribute(tile_pers_kernel, cudaFuncAttributeMaxDynamicSharedMemorySize, dyn);

    prep_kernel<<<GRID, 256>>>(emb, label, N);
    tile_pers_kernel<<<GRID, NTHR, dyn>>>((float*)d_out, N, T);
}

// round 15
// speedup vs baseline: 1.0258x; 1.0258x over previous
#include <cuda_runtime.h>
#include <cuda_bf16.h>
#include <math.h>
#include <stdint.h>

#define MAXN    8192
#define TILE    128
#define RSTRIDE 272                                // 256B row + 16B pad (conflict-free ldmatrix)
#define ARRB    (128 * RSTRIDE)                    // 34816 B per tile array
#define GRID    148
#define NTHR    1024
#define MAXG    (MAXN / 32)                        // 256 label groups

// ---------------- device scratch (allocation-free) ----------------
__device__ __nv_bfloat16 g_hi[MAXN * 128];
__device__ __nv_bfloat16 g_lo[MAXN * 128];
__device__ int   g_c0;
__device__ float g_part[GRID * 2];
__device__ int   g_done;                           // final-sum ticket (self-reset)

__device__ __forceinline__ uint32_t smem_u32(const void* p) {
    uint32_t a;
    asm("{ .reg .u64 t; cvta.to.shared.u64 t, %1; cvt.u32.u64 %0, t; }" : "=r"(a) : "l"(p));
    return a;
}
__device__ __forceinline__ void ldsm_x4(uint32_t* r, uint32_t addr) {
    asm volatile("ldmatrix.sync.aligned.m8n8.x4.shared.b16 {%0,%1,%2,%3}, [%4];"
                 : "=r"(r[0]), "=r"(r[1]), "=r"(r[2]), "=r"(r[3]) : "r"(addr));
}
__device__ __forceinline__ void mma16816(float* d, const uint32_t* a, const uint32_t* b) {
    asm volatile("mma.sync.aligned.m16n8k16.row.col.f32.bf16.bf16.f32 "
                 "{%0,%1,%2,%3}, {%4,%5,%6,%7}, {%8,%9}, {%0,%1,%2,%3};"
                 : "+f"(d[0]), "+f"(d[1]), "+f"(d[2]), "+f"(d[3])
                 : "r"(a[0]), "r"(a[1]), "r"(a[2]), "r"(a[3]), "r"(b[0]), "r"(b[1]));
}
__device__ __forceinline__ void cp16(uint32_t dst, const void* src, bool v) {
    asm volatile("cp.async.cg.shared.global [%0], [%1], 16, %2;"
                 :: "r"(dst), "l"(src), "r"(v ? 16 : 0) : "memory");
}
#define CP_COMMIT()  asm volatile("cp.async.commit_group;" ::: "memory")
#define CP_WAIT1()   asm volatile("cp.async.wait_group 1;" ::: "memory")
#define CP_WAIT0()   asm volatile("cp.async.wait_group 0;" ::: "memory")

// ---------------------------------------------------------------------------
// Kernel 1: prep — per-block redundant group counts + scan, then normalize/
// split/scatter this block's row slice into grouped order. 148 blocks x 256.
// ---------------------------------------------------------------------------
__global__ __launch_bounds__(256) void prep_kernel(
    const float* __restrict__ emb, const int* __restrict__ label, int N)
{
    const int tid = threadIdx.x, wid = tid >> 5, lane = tid & 31;
    const int NG = (N + 31) >> 5;

    __shared__ int s_pref[MAXG];
    __shared__ int s_wsum[8];
    __shared__ int s_c0;

    {
        int c = 0;
        if (tid < NG) {
            const int b0 = tid * 32;
            if (b0 + 32 <= N) {
                const int4* p = (const int4*)(label + b0);
                #pragma unroll
                for (int i = 0; i < 8; i++) {
                    const int4 v = p[i];
                    c += (v.x == 0) + (v.y == 0) + (v.z == 0) + (v.w == 0);
                }
            } else {
                for (int i = b0; i < N; i++) c += (label[i] == 0);
            }
        }
        int incl = c;
        #pragma unroll
        for (int o = 1; o < 32; o <<= 1) {
            int v = __shfl_up_sync(0xffffffffu, incl, o);
            if (lane >= o) incl += v;
        }
        if (lane == 31) s_wsum[wid] = incl;
        __syncthreads();
        if (wid == 0 && lane < 8) {
            int v = s_wsum[lane];
            #pragma unroll
            for (int o = 1; o < 8; o <<= 1) {
                int u = __shfl_up_sync(0xffu, v, o);
                if (lane >= o) v += u;
            }
            s_wsum[lane] = v;
        }
        __syncthreads();
        incl += (wid > 0) ? s_wsum[wid - 1] : 0;
        if (tid < NG) s_pref[tid] = incl - c;
        if (tid == 0) {
            s_c0 = s_wsum[7];
            if (blockIdx.x == 0) g_c0 = s_wsum[7];
        }
        __syncthreads();
    }
    const int C0 = s_c0;

    const int rowsPer = (N + gridDim.x - 1) / gridDim.x;
    const int r0 = blockIdx.x * rowsPer;
    const int r1 = min(r0 + rowsPer, N);
    for (int r = r0 + wid; r < r1; r += 8) {
        const int g = r >> 5;
        const int idx = g * 32 + lane;
        const int l = (idx < N) ? label[idx] : 1;
        const unsigned bal = __ballot_sync(0xffffffffu, l == 0);
        const int below = __popc(bal & ((1u << (r & 31)) - 1u));
        const int myl = __shfl_sync(0xffffffffu, l, r & 31);
        const int rank0 = s_pref[g] + below;
        const int dst = (myl == 0) ? rank0 : C0 + (r - rank0);

        float4 v = ((const float4*)(emb + (size_t)r * 128))[lane];
        float ss = v.x * v.x + v.y * v.y + v.z * v.z + v.w * v.w;
        #pragma unroll
        for (int o = 16; o; o >>= 1) ss += __shfl_xor_sync(0xffffffffu, ss, o);
        const float scale = 1.0f / fmaxf(sqrtf(ss), 1e-12f);
        float x[4] = {v.x * scale, v.y * scale, v.z * scale, v.w * scale};
        __nv_bfloat16 h[4], lo[4];
        #pragma unroll
        for (int i = 0; i < 4; i++) {
            h[i]  = __float2bfloat16(x[i]);
            lo[i] = __float2bfloat16(x[i] - __bfloat162float(h[i]));
        }
        uint2 ph, pl;
        ph.x = (uint32_t)__bfloat16_as_ushort(h[0])  | ((uint32_t)__bfloat16_as_ushort(h[1])  << 16);
        ph.y = (uint32_t)__bfloat16_as_ushort(h[2])  | ((uint32_t)__bfloat16_as_ushort(h[3])  << 16);
        pl.x = (uint32_t)__bfloat16_as_ushort(lo[0]) | ((uint32_t)__bfloat16_as_ushort(lo[1]) << 16);
        pl.y = (uint32_t)__bfloat16_as_ushort(lo[2]) | ((uint32_t)__bfloat16_as_ushort(lo[3]) << 16);
        ((uint2*)(g_hi + (size_t)dst * 128))[lane] = ph;
        ((uint2*)(g_lo + (size_t)dst * 128))[lane] = pl;
    }
}

// ---------------------------------------------------------------------------
// Kernel 2: persistent HMMA split-GEMM, 1024 threads (32 warps 8x4, 16x32/warp)
// Small per-warp footprint -> 8 warps/SMSP for latency hiding.
// ---------------------------------------------------------------------------
__device__ __forceinline__ void issue_tile(uint32_t dHi, uint32_t dLo, int b0, int N, int tid) {
    #pragma unroll
    for (int it = 0; it < 2; it++) {
        const int c = tid + it * NTHR;
        const int row = c >> 4, col16 = c & 15;
        const uint32_t off = (uint32_t)row * RSTRIDE + (uint32_t)col16 * 16;
        const int gr = b0 * TILE + row;
        const bool v = gr < N;
        const size_t g = (size_t)min(gr, N - 1) * 128 + col16 * 8;
        cp16(dHi + off, g_hi + g, v);
        cp16(dLo + off, g_lo + g, v);
    }
}

__global__ __launch_bounds__(NTHR, 1) void tile_pers_kernel(float* __restrict__ out, int N, int T) {
    const int tid = threadIdx.x, wid = tid >> 5, lane = tid & 31;
    const int C0 = g_c0;
    const int bx  = C0 >> 7;                       // label-boundary tile index
    const int C1s = (C0 + TILE - 1) >> 7;
    const int F0  = bx;
    const int nvalid = T * (T + 1) / 2 - F0 * (T - C1s);
    const int G = gridDim.x;
    const int q = nvalid / G, rmd = nvalid % G;
    const int start = blockIdx.x * q + min((int)blockIdx.x, rmd);
    const int end   = start + q + ((int)blockIdx.x < rmd ? 1 : 0);

    extern __shared__ char dsm[];
    const uint32_t base = smem_u32(dsm);
    const uint32_t sAh = base, sAl = base + ARRB;
    const uint32_t sBh0 = base + 2 * ARRB, sBl0 = base + 3 * ARRB;
    const uint32_t sBh1 = base + 4 * ARRB, sBl1 = base + 5 * ARRB;
    float* red = (float*)(dsm + 6 * ARRB);

    const int wm = wid & 7, wn = wid >> 3;         // 8x4 warp grid, 16x32 per warp
    const uint32_t aLaneOff = (uint32_t)(wm * 16 + (lane & 15)) * RSTRIDE + (uint32_t)(lane >> 4) * 16;
    const uint32_t bLaneOff = (uint32_t)(wn * 32 + ((lane >> 4) & 1) * 8 + (lane & 7)) * RSTRIDE
                            + (uint32_t)((lane >> 3) & 1) * 16;
    const int rIn = lane >> 2, cIn = (lane & 3) * 2;

    float s0 = 0.0f, s1 = 0.0f;

    if (start < end) {
        int bi = 0, bj = 0, k = 0;
        for (;;) {
            const int rowEnd = (bi < F0) ? C1s : T;
            const int cnt = rowEnd - bi;
            if (k + cnt > start) { bj = bi + (start - k); break; }
            k += cnt; bi++;
        }
        int pbi = bi, pbj = bj;
        if (pbi != pbj) issue_tile(sBh0, sBl0, pbj, N, tid);
        CP_COMMIT();

        int curA = -1;
        for (int idx = start; idx < end; idx++) {
            const int buf = (idx - start) & 1;
            const uint32_t cBh = buf ? sBh1 : sBh0, cBl = buf ? sBl1 : sBl0;
            const uint32_t nBh = buf ? sBh0 : sBh1, nBl = buf ? sBl0 : sBl1;
            const bool diag = (bi == bj);

            if (idx + 1 < end) {
                pbj++;
                const int rowEnd = (pbi < F0) ? C1s : T;
                if (pbj >= rowEnd) { pbi++; pbj = pbi; }
                if (pbi != pbj) issue_tile(nBh, nBl, pbj, N, tid);
            }
            CP_COMMIT();
            CP_WAIT1();
            __syncthreads();

            if (bi != curA) {
                issue_tile(sAh, sAl, bi, N, tid);
                CP_COMMIT();
                CP_WAIT0();
                curA = bi;
                __syncthreads();
            }

            const uint32_t bH = diag ? sAh : cBh;
            const uint32_t bL = diag ? sAl : cBl;
            const int rb = bi * TILE, cb = bj * TILE;
            const int wr0 = rb + wm * 16, wc0 = cb + wn * 32;
            const bool boundary = (bi == bx) || (bj == bx) || (rb + TILE > N) || (cb + TILE > N);
            const bool skipWarp = (wr0 > wc0 + 31) || (wr0 + 15 < C0 && wc0 >= C0);

            if (!skipWarp) {
                float acc[4][4];
                #pragma unroll
                for (int nt = 0; nt < 4; nt++)
                    #pragma unroll
                    for (int p = 0; p < 4; p++) acc[nt][p] = 0.0f;

                #pragma unroll
                for (int kk = 0; kk < 8; kk++) {
                    const uint32_t kB = (uint32_t)kk * 32;
                    uint32_t ah[4], al[4], bh[2][4], bl[2][4];
                    ldsm_x4(ah, sAh + aLaneOff + kB);
                    ldsm_x4(al, sAl + aLaneOff + kB);
                    #pragma unroll
                    for (int np = 0; np < 2; np++) {
                        const uint32_t bo = bLaneOff + (uint32_t)np * 16 * RSTRIDE + kB;
                        ldsm_x4(bh[np], bH + bo);
                        ldsm_x4(bl[np], bL + bo);
                    }
                    // term-major; per-acc order stays hh(k), hl(k), lh(k)
                    #pragma unroll
                    for (int nt = 0; nt < 4; nt++)
                        mma16816(acc[nt], ah, &bh[nt >> 1][(nt & 1) * 2]);
                    #pragma unroll
                    for (int nt = 0; nt < 4; nt++)
                        mma16816(acc[nt], ah, &bl[nt >> 1][(nt & 1) * 2]);
                    #pragma unroll
                    for (int nt = 0; nt < 4; nt++)
                        mma16816(acc[nt], al, &bh[nt >> 1][(nt & 1) * 2]);
                }

                if (!boundary && !diag) {
                    float t = 0.0f;
                    #pragma unroll
                    for (int nt = 0; nt < 4; nt++)
                        #pragma unroll
                        for (int p = 0; p < 4; p++)
                            t += __expf(acc[nt][p] * 10.0f);
                    if (rb < C0) s0 += t; else s1 += t;
                } else if (!boundary) {
                    float t = 0.0f;
                    #pragma unroll
                    for (int nt = 0; nt < 4; nt++) {
                        const int gi0 = wr0, gj0 = wc0 + nt * 8;
                        if (gi0 >= gj0 + 7) continue;
                        #pragma unroll
                        for (int p = 0; p < 4; p++) {
                            const int gi = gi0 + rIn + (p >> 1) * 8;
                            const int gj = gj0 + cIn + (p & 1);
                            if (gi < gj) t += __expf(acc[nt][p] * 10.0f);
                        }
                    }
                    if (rb < C0) s0 += t; else s1 += t;
                } else {
                    #pragma unroll
                    for (int nt = 0; nt < 4; nt++) {
                        const int gi0 = wr0, gj0 = wc0 + nt * 8;
                        if (gi0 >= gj0 + 7) continue;
                        if (gi0 + 15 < C0 && gj0 >= C0) continue;
                        #pragma unroll
                        for (int p = 0; p < 4; p++) {
                            const int gi = gi0 + rIn + (p >> 1) * 8;
                            const int gj = gj0 + cIn + (p & 1);
                            const bool i0 = gi < C0;
                            if (gi < N && gj < N && gi < gj && ((gj < C0) == i0)) {
                                const float e = __expf(acc[nt][p] * 10.0f);
                                if (i0) s0 += e; else s1 += e;
                            }
                        }
                    }
                }
            }
            __syncthreads();

            bj++;
            const int rowEnd = (bi < F0) ? C1s : T;
            if (bj >= rowEnd) { bi++; bj = bi; }
        }
    }

    // per-block deterministic reduction (1024 threads)
    red[tid] = s0; __syncthreads();
    for (int o = 512; o; o >>= 1) { if (tid < o) red[tid] += red[tid + o]; __syncthreads(); }
    if (tid == 0) g_part[blockIdx.x * 2] = red[0];
    __syncthreads();
    red[tid] = s1; __syncthreads();
    for (int o = 512; o; o >>= 1) { if (tid < o) red[tid] += red[tid + o]; __syncthreads(); }
    if (tid == 0) g_part[blockIdx.x * 2 + 1] = red[0];

    // last-block final reduction (ticket; nobody waits -> hang-free)
    __shared__ int s_ticket;
    __threadfence();
    if (tid == 0) s_ticket = atomicAdd(&g_done, 1);
    __syncthreads();
    if (s_ticket == G - 1) {
        __threadfence();
        float t0 = 0.0f, t1 = 0.0f;
        for (int b = tid; b < G; b += NTHR) { t0 += g_part[2 * b]; t1 += g_part[2 * b + 1]; }
        red[tid] = t0; __syncthreads();
        for (int o = 512; o; o >>= 1) { if (tid < o) red[tid] += red[tid + o]; __syncthreads(); }
        t0 = red[0]; __syncthreads();
        red[tid] = t1; __syncthreads();
        for (int o = 512; o; o >>= 1) { if (tid < o) red[tid] += red[tid + o]; __syncthreads(); }
        if (tid == 0) {
            const int c0n = C0, c1n = N - C0;
            float res = 0.0f;
            if (c0n > 1) res += 2.0f * t0 / (float)(c0n - 1);
            if (c1n > 1) res += 2.0f * red[0] / (float)(c1n - 1);
            out[0] = res;
            g_done = 0;                            // reset for next graph replay
        }
    }
}

// ---------------------------------------------------------------------------
extern "C" void kernel_launch(void* const* d_in, const int* in_sizes, int n_in,
                              void* d_out, int out_size) {
    const float* emb   = (const float*)d_in[0];
    const int*   label = (const int*)d_in[1];
    const int N = in_sizes[1];
    const int T = (N + TILE - 1) / TILE;
    const int dyn = 6 * ARRB + 4096;               // 212992 B

    cudaFuncSetAttribute(tile_pers_kernel, cudaFuncAttributeMaxDynamicSharedMemorySize, dyn);

    prep_kernel<<<GRID, 256>>>(emb, label, N);
    tile_pers_kernel<<<GRID, NTHR, dyn>>>((float*)d_out, N, T);
}